// round 14
// baseline (speedup 1.0000x reference)
#include <cuda_runtime.h>
#include <cuda_bf16.h>
#include <cstdint>
#include <math.h>

#define C_DIM   512
#define CH_DIM  128
#define HW_DIM  9216
#define B_DIM   16
#define TILE_PIX 64
#define KCHUNK   64
#define NCHUNK  (C_DIM / KCHUNK)    // 8
#define NTILES  (HW_DIM / TILE_PIX) // 144

// ---------------- portable tensor-core wrappers -------
static __device__ __forceinline__ void ldsm_x4(uint32_t* r, uint32_t addr) {
    asm volatile("ldmatrix.sync.aligned.m8n8.x4.shared.b16 {%0,%1,%2,%3}, [%4];"
                 : "=r"(r[0]), "=r"(r[1]), "=r"(r[2]), "=r"(r[3]) : "r"(addr));
}
static __device__ __forceinline__ void ldsm_x2_t(uint32_t* r, uint32_t addr) {
    asm volatile("ldmatrix.sync.aligned.m8n8.x2.trans.shared.b16 {%0,%1}, [%2];"
                 : "=r"(r[0]), "=r"(r[1]) : "r"(addr));
}
static __device__ __forceinline__ void mma_bf16(float* d, const uint32_t* a, const uint32_t* b) {
    asm volatile("mma.sync.aligned.m16n8k16.row.col.f32.bf16.bf16.f32 "
                 "{%0,%1,%2,%3}, {%4,%5,%6,%7}, {%8,%9}, {%0,%1,%2,%3};"
                 : "+f"(d[0]), "+f"(d[1]), "+f"(d[2]), "+f"(d[3])
                 : "r"(a[0]), "r"(a[1]), "r"(a[2]), "r"(a[3]), "r"(b[0]), "r"(b[1]));
}
static __device__ __forceinline__ uint32_t smem_u32(const void* p) {
    uint32_t a;
    asm("{ .reg .u64 t; cvta.to.shared.u64 t, %1; cvt.u32.u64 %0, t; }" : "=r"(a) : "l"(p));
    return a;
}

#define CP16(dst, src) \
    asm volatile("cp.async.cg.shared.global [%0], [%1], 16;" :: "r"(dst), "l"(src) : "memory")
#define CP_COMMIT() asm volatile("cp.async.commit_group;" ::: "memory")
#define CP_WAIT0()  asm volatile("cp.async.wait_group 0;" ::: "memory")

// weight tile images, SW128-XOR swizzled [chunk][hi|lo][128 o x 64 k bf16]
__device__ __align__(16) __nv_bfloat16 g_wt[NCHUNK][2][CH_DIM * KCHUNK];

__global__ void lcs_prep_w(const float* __restrict__ w1) {
    int idx = blockIdx.x * blockDim.x + threadIdx.x;   // 0..65535
    int o = idx >> 9;
    int c = idx & 511;
    int ch = c >> 6;
    int k  = c & 63;
    float w = w1[o * C_DIM + c];
    uint32_t wb;
    memcpy(&wb, &w, 4);
    uint32_t hb = wb & 0xFFFF0000u;
    float hf;
    memcpy(&hf, &hb, 4);
    __nv_bfloat16 hi = __ushort_as_bfloat16((unsigned short)(hb >> 16));
    __nv_bfloat16 lo = __float2bfloat16(w - hf);
    uint32_t off = (uint32_t)o * 128u + (uint32_t)k * 2u;
    uint32_t sw  = off ^ ((off >> 3) & 0x70u);
    g_wt[ch][0][sw >> 1] = hi;
    g_wt[ch][1][sw >> 1] = lo;
}

// 48KB dynamic smem: [Wh 16K][Wl 16K][Xh 8K][Xl 8K]
extern __shared__ char dynsmem[];

__global__ __launch_bounds__(256, 3)
void lcs_main(const float* __restrict__ x,
              const float* __restrict__ b1,
              const float* __restrict__ w2,
              const float* __restrict__ b2,
              float* __restrict__ out) {
    __shared__ float logit_s[TILE_PIX];
    __shared__ __align__(16) float m0_s[TILE_PIX];
    __shared__ __align__(16) float m1_s[TILE_PIX];

    const int tid  = threadIdx.x;
    const int wid  = tid >> 5;
    const int lane = tid & 31;
    const int b    = blockIdx.x / NTILES;
    const int tile = blockIdx.x % NTILES;
    const int pix0 = tile * TILE_PIX;

    const float* xb = x + (size_t)b * C_DIM * HW_DIM + pix0;

    const uint32_t smem = smem_u32(dynsmem);
    const uint32_t sWh = smem, sWl = smem + 16384;
    const uint32_t sXh = smem + 32768, sXl = smem + 40960;

    if (tid < TILE_PIX) logit_s[tid] = 0.0f;

    // warp tile: wo in {0,1} -> 64 outs, wp in {0..3} -> 16 pixels
    const int wo = wid & 1;
    const int wp = wid >> 1;
    const int o0 = wo * 64;
    const int p0 = wp * 16;

    float acc[4][2][4];
#pragma unroll
    for (int mt = 0; mt < 4; mt++)
#pragma unroll
        for (int nt = 0; nt < 2; nt++)
#pragma unroll
            for (int q = 0; q < 4; q++) acc[mt][nt][q] = 0.0f;

    uint32_t aBase[4];
#pragma unroll
    for (int mt = 0; mt < 4; mt++)
        aBase[mt] = (uint32_t)(o0 + mt * 16 + (lane & 15)) * 128u + (uint32_t)(lane >> 4) * 16u;

    // ---- pipeline helpers ----
    const int l16   = tid & 15;          // 16B segment within 64-px row
    const int krow4 = tid >> 4;          // base k row (0..15), rows k = kk*16 + krow4

    float4 xr[4];                        // register staging for next chunk's x

    auto ldg_x = [&](int chunk) {
        const float* src = xb + (size_t)(chunk * KCHUNK + krow4) * HW_DIM + l16 * 4;
#pragma unroll
        for (int kk = 0; kk < 4; kk++) {
            asm volatile("ld.global.nc.v4.f32 {%0,%1,%2,%3}, [%4];"
                         : "=f"(xr[kk].x), "=f"(xr[kk].y), "=f"(xr[kk].z), "=f"(xr[kk].w)
                         : "l"(src + (size_t)kk * 16 * HW_DIM));
        }
    };
    auto cp_w = [&](int chunk) {
        const char* wsrc = (const char*)&g_wt[chunk][0][0];
#pragma unroll
        for (int i = 0; i < 8; i++)
            CP16(sWh + (uint32_t)(tid * 16 + i * 4096), wsrc + tid * 16 + i * 4096);
    };
    auto convert_x = [&]() {
#pragma unroll
        for (int kk = 0; kk < 4; kk++) {
            const int k = kk * 16 + krow4;
            float4 v = xr[kk];
            uint32_t b0, b1_, b2_, b3;
            memcpy(&b0, &v.x, 4); memcpy(&b1_, &v.y, 4);
            memcpy(&b2_, &v.z, 4); memcpy(&b3, &v.w, 4);
            uint32_t h01 = __byte_perm(b0, b1_, 0x7632);
            uint32_t h23 = __byte_perm(b2_, b3, 0x7632);
            uint32_t t0 = b0 & 0xFFFF0000u, t1 = b1_ & 0xFFFF0000u;
            uint32_t t2 = b2_ & 0xFFFF0000u, t3 = b3 & 0xFFFF0000u;
            float f0, f1, f2, f3;
            memcpy(&f0, &t0, 4); memcpy(&f1, &t1, 4);
            memcpy(&f2, &t2, 4); memcpy(&f3, &t3, 4);
            __nv_bfloat162 lo01 = __floats2bfloat162_rn(v.x - f0, v.y - f1);
            __nv_bfloat162 lo23 = __floats2bfloat162_rn(v.z - f2, v.w - f3);
            uint32_t l01, l23;
            memcpy(&l01, &lo01, 4); memcpy(&l23, &lo23, 4);
            uint32_t addr = (uint32_t)k * 128u
                          + (uint32_t)((((uint32_t)(l16 >> 1)) ^ (k & 7)) << 4)
                          + (uint32_t)((l16 & 1) << 3);
            asm volatile("st.shared.v2.b32 [%0], {%1,%2};" :: "r"(sXh + addr), "r"(h01), "r"(h23) : "memory");
            asm volatile("st.shared.v2.b32 [%0], {%1,%2};" :: "r"(sXl + addr), "r"(l01), "r"(l23) : "memory");
        }
    };

    // ---- prologue: stage chunk 0 ----
    ldg_x(0);
    cp_w(0);
    CP_COMMIT();
    convert_x();
    CP_WAIT0();
    __syncthreads();

    for (int chunk = 0; chunk < NCHUNK; chunk++) {
        // prefetch next chunk's x into registers; MMA phase covers the latency
        if (chunk < NCHUNK - 1) ldg_x(chunk + 1);

        // ---- MMA: 4 k-steps of 16, 3 terms ----
#pragma unroll
        for (int ks = 0; ks < 4; ks++) {
            uint32_t ah[4][4], bh[2][2], bl[2][2];
#pragma unroll
            for (int mt = 0; mt < 4; mt++) {
                uint32_t off = aBase[mt] + (uint32_t)ks * 32u;
                ldsm_x4(ah[mt], sWh + (off ^ ((off >> 3) & 0x70u)));
            }
            const uint32_t kRow = (uint32_t)(ks * 16 + (lane & 15));
#pragma unroll
            for (int nt = 0; nt < 2; nt++) {
                uint32_t addr = kRow * 128u
                              + (uint32_t)((((uint32_t)(wp * 2 + nt)) ^ (kRow & 7u)) << 4);
                ldsm_x2_t(bh[nt], sXh + addr);
                ldsm_x2_t(bl[nt], sXl + addr);
            }
#pragma unroll
            for (int mt = 0; mt < 4; mt++)
#pragma unroll
                for (int nt = 0; nt < 2; nt++) {
                    mma_bf16(acc[mt][nt], ah[mt], bh[nt]);
                    mma_bf16(acc[mt][nt], ah[mt], bl[nt]);
                }
#pragma unroll
            for (int mt = 0; mt < 4; mt++) {
                uint32_t off = aBase[mt] + (uint32_t)ks * 32u;
                ldsm_x4(ah[mt], sWl + (off ^ ((off >> 3) & 0x70u)));
            }
#pragma unroll
            for (int mt = 0; mt < 4; mt++)
#pragma unroll
                for (int nt = 0; nt < 2; nt++)
                    mma_bf16(acc[mt][nt], ah[mt], bh[nt]);
        }

        __syncthreads();   // MMA done reading W, Xh, Xl

        if (chunk < NCHUNK - 1) {
            cp_w(chunk + 1);      // W buffer free now; fetch overlaps convert below
            CP_COMMIT();
            convert_x();          // registers -> Xh/Xl (independent of W arrival)
            CP_WAIT0();
            __syncthreads();
        }
    }

    // ---- epilogue: logits d = sum_o (w2[0][o]-w2[1][o]) * relu(h + b1[o]) ----
    float wdv[8], b1v[8];
#pragma unroll
    for (int mt = 0; mt < 4; mt++)
#pragma unroll
        for (int h = 0; h < 2; h++) {
            int o = o0 + mt * 16 + (lane >> 2) + h * 8;
            wdv[mt * 2 + h] = w2[o] - w2[CH_DIM + o];
            b1v[mt * 2 + h] = b1[o];
        }

    float part[2][2];
#pragma unroll
    for (int nt = 0; nt < 2; nt++)
#pragma unroll
        for (int c = 0; c < 2; c++) {
            float s = 0.0f;
#pragma unroll
            for (int mt = 0; mt < 4; mt++)
#pragma unroll
                for (int h = 0; h < 2; h++)
                    s += wdv[mt * 2 + h] * fmaxf(acc[mt][nt][h * 2 + c] + b1v[mt * 2 + h], 0.0f);
            part[nt][c] = s;
        }
#pragma unroll
    for (int off = 4; off < 32; off <<= 1)
#pragma unroll
        for (int nt = 0; nt < 2; nt++)
#pragma unroll
            for (int c = 0; c < 2; c++)
                part[nt][c] += __shfl_xor_sync(0xFFFFFFFFu, part[nt][c], off);

    if (lane < 4) {
#pragma unroll
        for (int nt = 0; nt < 2; nt++)
#pragma unroll
            for (int c = 0; c < 2; c++)
                atomicAdd(&logit_s[p0 + nt * 8 + lane * 2 + c], part[nt][c]);
    }
    __syncthreads();

    const float db2 = b2[0] - b2[1];
    const size_t OFFX = (size_t)B_DIM * C_DIM * HW_DIM;
    if (tid < TILE_PIX) {
        float d  = logit_s[tid] + db2;
        float m0 = 1.0f / (1.0f + expf(-d));
        m0_s[tid] = m0;
        m1_s[tid] = 1.0f - m0;
        float* mout = out + 2 * OFFX + (size_t)b * 2 * HW_DIM + pix0 + tid;
        mout[0]      = m0;
        mout[HW_DIM] = 1.0f - m0;
    }
    __syncthreads();

    // ---- multiply sweep: x0 = x*m0, x1 = x*m1 ----
    float* out0 = out + (size_t)b * C_DIM * HW_DIM + pix0;
    float* out1 = out0 + OFFX;
    const float4* m0v4 = (const float4*)m0_s;
    const float4* m1v4 = (const float4*)m1_s;

    for (int it = tid; it < C_DIM * (TILE_PIX / 4); it += 256) {
        int c    = it >> 4;
        int col4 = it & 15;
        size_t off = (size_t)c * HW_DIM + col4 * 4;
        float4 xv;
        asm volatile("ld.global.cs.v4.f32 {%0,%1,%2,%3}, [%4];"
                     : "=f"(xv.x), "=f"(xv.y), "=f"(xv.z), "=f"(xv.w)
                     : "l"(xb + off));
        float4 m0v = m0v4[col4];
        float4 m1v = m1v4[col4];
        float4 r0 = make_float4(xv.x * m0v.x, xv.y * m0v.y, xv.z * m0v.z, xv.w * m0v.w);
        float4 r1 = make_float4(xv.x * m1v.x, xv.y * m1v.y, xv.z * m1v.z, xv.w * m1v.w);
        asm volatile("st.global.cs.v4.f32 [%0], {%1,%2,%3,%4};"
                     :: "l"(out0 + off), "f"(r0.x), "f"(r0.y), "f"(r0.z), "f"(r0.w) : "memory");
        asm volatile("st.global.cs.v4.f32 [%0], {%1,%2,%3,%4};"
                     :: "l"(out1 + off), "f"(r1.x), "f"(r1.y), "f"(r1.z), "f"(r1.w) : "memory");
    }
}

extern "C" void kernel_launch(void* const* d_in, const int* in_sizes, int n_in,
                              void* d_out, int out_size) {
    const float* x  = (const float*)d_in[0];
    const float* w1 = (const float*)d_in[1];
    const float* b1 = (const float*)d_in[2];
    const float* w2 = (const float*)d_in[3];
    const float* b2 = (const float*)d_in[4];
    float* out = (float*)d_out;

    cudaFuncSetAttribute(lcs_main, cudaFuncAttributeMaxDynamicSharedMemorySize, 49152);

    lcs_prep_w<<<256, 256>>>(w1);

    int nblocks = B_DIM * NTILES;   // 16 * 144 = 2304
    lcs_main<<<nblocks, 256, 49152>>>(x, b1, w2, b2, out);
}

// round 15
// speedup vs baseline: 1.0837x; 1.0837x over previous
#include <cuda_runtime.h>
#include <cuda_bf16.h>
#include <cstdint>
#include <math.h>

#define C_DIM   512
#define CH_DIM  128
#define HW_DIM  9216
#define B_DIM   16
#define TILE_PIX 64
#define KCHUNK   64
#define NCHUNK  (C_DIM / KCHUNK)    // 8
#define NTILES  (HW_DIM / TILE_PIX) // 144

// ---------------- portable tensor-core wrappers -------
static __device__ __forceinline__ void ldsm_x4(uint32_t* r, uint32_t addr) {
    asm volatile("ldmatrix.sync.aligned.m8n8.x4.shared.b16 {%0,%1,%2,%3}, [%4];"
                 : "=r"(r[0]), "=r"(r[1]), "=r"(r[2]), "=r"(r[3]) : "r"(addr));
}
static __device__ __forceinline__ void ldsm_x2_t(uint32_t* r, uint32_t addr) {
    asm volatile("ldmatrix.sync.aligned.m8n8.x2.trans.shared.b16 {%0,%1}, [%2];"
                 : "=r"(r[0]), "=r"(r[1]) : "r"(addr));
}
static __device__ __forceinline__ void mma_bf16(float* d, const uint32_t* a, const uint32_t* b) {
    asm volatile("mma.sync.aligned.m16n8k16.row.col.f32.bf16.bf16.f32 "
                 "{%0,%1,%2,%3}, {%4,%5,%6,%7}, {%8,%9}, {%0,%1,%2,%3};"
                 : "+f"(d[0]), "+f"(d[1]), "+f"(d[2]), "+f"(d[3])
                 : "r"(a[0]), "r"(a[1]), "r"(a[2]), "r"(a[3]), "r"(b[0]), "r"(b[1]));
}
static __device__ __forceinline__ uint32_t smem_u32(const void* p) {
    uint32_t a;
    asm("{ .reg .u64 t; cvta.to.shared.u64 t, %1; cvt.u32.u64 %0, t; }" : "=r"(a) : "l"(p));
    return a;
}

#define CP16(dst, src) \
    asm volatile("cp.async.cg.shared.global [%0], [%1], 16;" :: "r"(dst), "l"(src) : "memory")
#define CP_COMMIT() asm volatile("cp.async.commit_group;" ::: "memory")
#define CP_WAIT0()  asm volatile("cp.async.wait_group 0;" ::: "memory")
#define CP_WAIT1()  asm volatile("cp.async.wait_group 1;" ::: "memory")

// weight tile images, SW128-XOR swizzled [chunk][hi|lo][128 o x 64 k bf16]
__device__ __align__(16) __nv_bfloat16 g_wt[NCHUNK][2][CH_DIM * KCHUNK];

__global__ void lcs_prep_w(const float* __restrict__ w1) {
    int idx = blockIdx.x * blockDim.x + threadIdx.x;   // 0..65535
    int o = idx >> 9;
    int c = idx & 511;
    int ch = c >> 6;
    int k  = c & 63;
    float w = w1[o * C_DIM + c];
    uint32_t wb;
    memcpy(&wb, &w, 4);
    uint32_t hb = wb & 0xFFFF0000u;
    float hf;
    memcpy(&hf, &hb, 4);
    __nv_bfloat16 hi = __ushort_as_bfloat16((unsigned short)(hb >> 16));
    __nv_bfloat16 lo = __float2bfloat16(w - hf);
    uint32_t off = (uint32_t)o * 128u + (uint32_t)k * 2u;
    uint32_t sw  = off ^ ((off >> 3) & 0x70u);
    g_wt[ch][0][sw >> 1] = hi;
    g_wt[ch][1][sw >> 1] = lo;
}

// 64KB dynamic smem: [Wh 16K][Wl 16K][Xh 8K][Xl 8K][Xraw 16K]
extern __shared__ char dynsmem[];

__global__ __launch_bounds__(256, 3)
void lcs_main(const float* __restrict__ x,
              const float* __restrict__ b1,
              const float* __restrict__ w2,
              const float* __restrict__ b2,
              float* __restrict__ out) {
    __shared__ float logit_s[TILE_PIX];
    __shared__ __align__(16) float m0_s[TILE_PIX];
    __shared__ __align__(16) float m1_s[TILE_PIX];

    const int tid  = threadIdx.x;
    const int wid  = tid >> 5;
    const int lane = tid & 31;
    const int b    = blockIdx.x / NTILES;
    const int tile = blockIdx.x % NTILES;
    const int pix0 = tile * TILE_PIX;

    // phase-stagger the K-chunk order across CTAs (sum is commutative);
    // co-resident CTAs then mix MMA / convert / load phases instead of lock-step.
    const int phase = blockIdx.x & 7;

    const float* xb = x + (size_t)b * C_DIM * HW_DIM + pix0;

    const uint32_t smem = smem_u32(dynsmem);
    const uint32_t sWh = smem, sWl = smem + 16384;
    const uint32_t sXh = smem + 32768, sXl = smem + 40960;
    const uint32_t sXraw = smem + 49152;

    if (tid < TILE_PIX) logit_s[tid] = 0.0f;

    // warp tile: wo in {0,1} -> 64 outs, wp in {0..3} -> 16 pixels
    const int wo = wid & 1;
    const int wp = wid >> 1;
    const int o0 = wo * 64;
    const int p0 = wp * 16;

    float acc[4][2][4];
#pragma unroll
    for (int mt = 0; mt < 4; mt++)
#pragma unroll
        for (int nt = 0; nt < 2; nt++)
#pragma unroll
            for (int q = 0; q < 4; q++) acc[mt][nt][q] = 0.0f;

    uint32_t aBase[4];
#pragma unroll
    for (int mt = 0; mt < 4; mt++)
        aBase[mt] = (uint32_t)(o0 + mt * 16 + (lane & 15)) * 128u + (uint32_t)(lane >> 4) * 16u;

    // ---- pipeline helpers ----
    const int xrow = tid >> 2;                 // 0..63
    const uint32_t xdst = sXraw + (uint32_t)xrow * 256u;

    auto cp_x = [&](int chunk) {
        const float* src = xb + (size_t)(chunk * KCHUNK + xrow) * HW_DIM;
#pragma unroll
        for (int i = 0; i < 4; i++) {
            int seg = (tid & 3) + i * 4;       // 0..15 (16B segments of 256B row)
            CP16(xdst + (uint32_t)seg * 16u, src + seg * 4);
        }
    };
    auto cp_w = [&](int chunk) {
        const char* wsrc = (const char*)&g_wt[chunk][0][0];
#pragma unroll
        for (int i = 0; i < 8; i++)
            CP16(sWh + (uint32_t)(tid * 16 + i * 4096), wsrc + tid * 16 + i * 4096);
    };
    auto convert_x = [&]() {
        const int l16 = tid & 15;
#pragma unroll
        for (int kk = 0; kk < 4; kk++) {
            const int k = kk * 16 + (tid >> 4);
            float4 v;
            asm volatile("ld.shared.v4.f32 {%0,%1,%2,%3}, [%4];"
                         : "=f"(v.x), "=f"(v.y), "=f"(v.z), "=f"(v.w)
                         : "r"(sXraw + (uint32_t)k * 256u + (uint32_t)l16 * 16u));
            uint32_t b0, b1_, b2_, b3;
            memcpy(&b0, &v.x, 4); memcpy(&b1_, &v.y, 4);
            memcpy(&b2_, &v.z, 4); memcpy(&b3, &v.w, 4);
            uint32_t h01 = __byte_perm(b0, b1_, 0x7632);
            uint32_t h23 = __byte_perm(b2_, b3, 0x7632);
            uint32_t t0 = b0 & 0xFFFF0000u, t1 = b1_ & 0xFFFF0000u;
            uint32_t t2 = b2_ & 0xFFFF0000u, t3 = b3 & 0xFFFF0000u;
            float f0, f1, f2, f3;
            memcpy(&f0, &t0, 4); memcpy(&f1, &t1, 4);
            memcpy(&f2, &t2, 4); memcpy(&f3, &t3, 4);
            __nv_bfloat162 lo01 = __floats2bfloat162_rn(v.x - f0, v.y - f1);
            __nv_bfloat162 lo23 = __floats2bfloat162_rn(v.z - f2, v.w - f3);
            uint32_t l01, l23;
            memcpy(&l01, &lo01, 4); memcpy(&l23, &lo23, 4);
            uint32_t addr = (uint32_t)k * 128u
                          + (uint32_t)((((uint32_t)(l16 >> 1)) ^ (k & 7)) << 4)
                          + (uint32_t)((l16 & 1) << 3);
            asm volatile("st.shared.v2.b32 [%0], {%1,%2};" :: "r"(sXh + addr), "r"(h01), "r"(h23) : "memory");
            asm volatile("st.shared.v2.b32 [%0], {%1,%2};" :: "r"(sXl + addr), "r"(l01), "r"(l23) : "memory");
        }
    };

    // ---- prologue: stage first chunk (id = phase) ----
    cp_x(phase);
    cp_w(phase);
    CP_COMMIT();
    CP_WAIT0();
    __syncthreads();
    convert_x();
    __syncthreads();

    for (int it = 0; it < NCHUNK; it++) {
        const int nxt = (it + 1 + phase) & 7;
        if (it < NCHUNK - 1) {
            cp_x(nxt);
            CP_COMMIT();          // group X
        }

        // ---- MMA: 4 k-steps of 16, 3 terms ----
#pragma unroll
        for (int ks = 0; ks < 4; ks++) {
            uint32_t ah[4][4], bh[2][2], bl[2][2];
#pragma unroll
            for (int mt = 0; mt < 4; mt++) {
                uint32_t off = aBase[mt] + (uint32_t)ks * 32u;
                ldsm_x4(ah[mt], sWh + (off ^ ((off >> 3) & 0x70u)));
            }
            const uint32_t kRow = (uint32_t)(ks * 16 + (lane & 15));
#pragma unroll
            for (int nt = 0; nt < 2; nt++) {
                uint32_t addr = kRow * 128u
                              + (uint32_t)((((uint32_t)(wp * 2 + nt)) ^ (kRow & 7u)) << 4);
                ldsm_x2_t(bh[nt], sXh + addr);
                ldsm_x2_t(bl[nt], sXl + addr);
            }
#pragma unroll
            for (int mt = 0; mt < 4; mt++)
#pragma unroll
                for (int nt = 0; nt < 2; nt++) {
                    mma_bf16(acc[mt][nt], ah[mt], bh[nt]);
                    mma_bf16(acc[mt][nt], ah[mt], bl[nt]);
                }
#pragma unroll
            for (int mt = 0; mt < 4; mt++) {
                uint32_t off = aBase[mt] + (uint32_t)ks * 32u;
                ldsm_x4(ah[mt], sWl + (off ^ ((off >> 3) & 0x70u)));
            }
#pragma unroll
            for (int mt = 0; mt < 4; mt++)
#pragma unroll
                for (int nt = 0; nt < 2; nt++)
                    mma_bf16(acc[mt][nt], ah[mt], bh[nt]);
        }

        __syncthreads();   // MMA done reading W, Xh, Xl (and prior Xraw reads done)

        if (it < NCHUNK - 1) {
            cp_w(nxt);
            CP_COMMIT();          // group W
            CP_WAIT1();           // X(nxt) landed; W may still be in flight
            __syncthreads();      // X visible to all threads
            convert_x();          // Xraw -> Xh/Xl, overlaps W fetch latency
            CP_WAIT0();           // W landed
            __syncthreads();      // W + converted X visible to all
        }
    }

    // ---- epilogue: logits d = sum_o (w2[0][o]-w2[1][o]) * relu(h + b1[o]) ----
    float wdv[8], b1v[8];
#pragma unroll
    for (int mt = 0; mt < 4; mt++)
#pragma unroll
        for (int h = 0; h < 2; h++) {
            int o = o0 + mt * 16 + (lane >> 2) + h * 8;
            wdv[mt * 2 + h] = w2[o] - w2[CH_DIM + o];
            b1v[mt * 2 + h] = b1[o];
        }

    float part[2][2];
#pragma unroll
    for (int nt = 0; nt < 2; nt++)
#pragma unroll
        for (int c = 0; c < 2; c++) {
            float s = 0.0f;
#pragma unroll
            for (int mt = 0; mt < 4; mt++)
#pragma unroll
                for (int h = 0; h < 2; h++)
                    s += wdv[mt * 2 + h] * fmaxf(acc[mt][nt][h * 2 + c] + b1v[mt * 2 + h], 0.0f);
            part[nt][c] = s;
        }
#pragma unroll
    for (int off = 4; off < 32; off <<= 1)
#pragma unroll
        for (int nt = 0; nt < 2; nt++)
#pragma unroll
            for (int c = 0; c < 2; c++)
                part[nt][c] += __shfl_xor_sync(0xFFFFFFFFu, part[nt][c], off);

    if (lane < 4) {
#pragma unroll
        for (int nt = 0; nt < 2; nt++)
#pragma unroll
            for (int c = 0; c < 2; c++)
                atomicAdd(&logit_s[p0 + nt * 8 + lane * 2 + c], part[nt][c]);
    }
    __syncthreads();

    const float db2 = b2[0] - b2[1];
    const size_t OFFX = (size_t)B_DIM * C_DIM * HW_DIM;
    if (tid < TILE_PIX) {
        float d  = logit_s[tid] + db2;
        float m0 = 1.0f / (1.0f + expf(-d));
        m0_s[tid] = m0;
        m1_s[tid] = 1.0f - m0;
        float* mout = out + 2 * OFFX + (size_t)b * 2 * HW_DIM + pix0 + tid;
        mout[0]      = m0;
        mout[HW_DIM] = 1.0f - m0;
    }
    __syncthreads();

    // ---- multiply sweep: x0 = x*m0, x1 = x*m1 ----
    float* out0 = out + (size_t)b * C_DIM * HW_DIM + pix0;
    float* out1 = out0 + OFFX;
    const float4* m0v4 = (const float4*)m0_s;
    const float4* m1v4 = (const float4*)m1_s;

    for (int it = tid; it < C_DIM * (TILE_PIX / 4); it += 256) {
        int c    = it >> 4;
        int col4 = it & 15;
        size_t off = (size_t)c * HW_DIM + col4 * 4;
        float4 xv;
        asm volatile("ld.global.cs.v4.f32 {%0,%1,%2,%3}, [%4];"
                     : "=f"(xv.x), "=f"(xv.y), "=f"(xv.z), "=f"(xv.w)
                     : "l"(xb + off));
        float4 m0v = m0v4[col4];
        float4 m1v = m1v4[col4];
        float4 r0 = make_float4(xv.x * m0v.x, xv.y * m0v.y, xv.z * m0v.z, xv.w * m0v.w);
        float4 r1 = make_float4(xv.x * m1v.x, xv.y * m1v.y, xv.z * m1v.z, xv.w * m1v.w);
        asm volatile("st.global.cs.v4.f32 [%0], {%1,%2,%3,%4};"
                     :: "l"(out0 + off), "f"(r0.x), "f"(r0.y), "f"(r0.z), "f"(r0.w) : "memory");
        asm volatile("st.global.cs.v4.f32 [%0], {%1,%2,%3,%4};"
                     :: "l"(out1 + off), "f"(r1.x), "f"(r1.y), "f"(r1.z), "f"(r1.w) : "memory");
    }
}

extern "C" void kernel_launch(void* const* d_in, const int* in_sizes, int n_in,
                              void* d_out, int out_size) {
    const float* x  = (const float*)d_in[0];
    const float* w1 = (const float*)d_in[1];
    const float* b1 = (const float*)d_in[2];
    const float* w2 = (const float*)d_in[3];
    const float* b2 = (const float*)d_in[4];
    float* out = (float*)d_out;

    cudaFuncSetAttribute(lcs_main, cudaFuncAttributeMaxDynamicSharedMemorySize, 65536);

    lcs_prep_w<<<256, 256>>>(w1);

    int nblocks = B_DIM * NTILES;   // 16 * 144 = 2304
    lcs_main<<<nblocks, 256, 65536>>>(x, b1, w2, b2, out);
}

// round 17
// speedup vs baseline: 1.1467x; 1.0581x over previous
#include <cuda_runtime.h>
#include <cuda_fp16.h>
#include <cstdint>
#include <math.h>

#define C_DIM   512
#define CH_DIM  128
#define HW_DIM  9216
#define B_DIM   16
#define TILE_PIX 64
#define KCHUNK   64
#define NCHUNK  (C_DIM / KCHUNK)    // 8
#define NTILES  (HW_DIM / TILE_PIX) // 144

// ---------------- portable tensor-core wrappers -------
static __device__ __forceinline__ void ldsm_x4(uint32_t* r, uint32_t addr) {
    asm volatile("ldmatrix.sync.aligned.m8n8.x4.shared.b16 {%0,%1,%2,%3}, [%4];"
                 : "=r"(r[0]), "=r"(r[1]), "=r"(r[2]), "=r"(r[3]) : "r"(addr));
}
static __device__ __forceinline__ void ldsm_x2_t(uint32_t* r, uint32_t addr) {
    asm volatile("ldmatrix.sync.aligned.m8n8.x2.trans.shared.b16 {%0,%1}, [%2];"
                 : "=r"(r[0]), "=r"(r[1]) : "r"(addr));
}
static __device__ __forceinline__ void mma_f16(float* d, const uint32_t* a, const uint32_t* b) {
    asm volatile("mma.sync.aligned.m16n8k16.row.col.f32.f16.f16.f32 "
                 "{%0,%1,%2,%3}, {%4,%5,%6,%7}, {%8,%9}, {%0,%1,%2,%3};"
                 : "+f"(d[0]), "+f"(d[1]), "+f"(d[2]), "+f"(d[3])
                 : "r"(a[0]), "r"(a[1]), "r"(a[2]), "r"(a[3]), "r"(b[0]), "r"(b[1]));
}
static __device__ __forceinline__ uint32_t smem_u32(const void* p) {
    uint32_t a;
    asm("{ .reg .u64 t; cvta.to.shared.u64 t, %1; cvt.u32.u64 %0, t; }" : "=r"(a) : "l"(p));
    return a;
}

#define CP16(dst, src) \
    asm volatile("cp.async.cg.shared.global [%0], [%1], 16;" :: "r"(dst), "l"(src) : "memory")
#define CP_COMMIT() asm volatile("cp.async.commit_group;" ::: "memory")
#define CP_WAIT0()  asm volatile("cp.async.wait_group 0;" ::: "memory")

// weight tile images, fp16, SW128-XOR swizzled: [chunk][128 o x 64 k]
__device__ __align__(16) __half g_wt[NCHUNK][CH_DIM * KCHUNK];

__global__ void lcs_prep_w(const float* __restrict__ w1) {
    int idx = blockIdx.x * blockDim.x + threadIdx.x;   // 0..65535
    int o = idx >> 9;
    int c = idx & 511;
    int ch = c >> 6;
    int k  = c & 63;
    float w = w1[o * C_DIM + c];
    uint32_t off = (uint32_t)o * 128u + (uint32_t)k * 2u;
    uint32_t sw  = off ^ ((off >> 3) & 0x70u);
    g_wt[ch][sw >> 1] = __float2half_rn(w);
}

// 48KB dynamic smem: [W 16K][Xh 8K][Xl 8K][Xraw 16K]
extern __shared__ char dynsmem[];

__global__ __launch_bounds__(256, 4)
void lcs_main(const float* __restrict__ x,
              const float* __restrict__ b1,
              const float* __restrict__ w2,
              const float* __restrict__ b2,
              float* __restrict__ out) {
    __shared__ float logit_s[TILE_PIX];
    __shared__ __align__(16) float m0_s[TILE_PIX];
    __shared__ __align__(16) float m1_s[TILE_PIX];

    const int tid  = threadIdx.x;
    const int wid  = tid >> 5;
    const int lane = tid & 31;
    const int b    = blockIdx.x / NTILES;
    const int tile = blockIdx.x % NTILES;
    const int pix0 = tile * TILE_PIX;

    const float* xb = x + (size_t)b * C_DIM * HW_DIM + pix0;

    const uint32_t smem = smem_u32(dynsmem);
    const uint32_t sW  = smem;
    const uint32_t sXh = smem + 16384, sXl = smem + 24576;
    const uint32_t sXraw = smem + 32768;

    if (tid < TILE_PIX) logit_s[tid] = 0.0f;

    // warp tile: wo in {0,1} -> 64 outs, wp in {0..3} -> 16 pixels
    const int wo = wid & 1;
    const int wp = wid >> 1;
    const int o0 = wo * 64;
    const int p0 = wp * 16;

    float acc[4][2][4];
#pragma unroll
    for (int mt = 0; mt < 4; mt++)
#pragma unroll
        for (int nt = 0; nt < 2; nt++)
#pragma unroll
            for (int q = 0; q < 4; q++) acc[mt][nt][q] = 0.0f;

    uint32_t aBase[4];
#pragma unroll
    for (int mt = 0; mt < 4; mt++)
        aBase[mt] = (uint32_t)(o0 + mt * 16 + (lane & 15)) * 128u + (uint32_t)(lane >> 4) * 16u;

    // ---- pipeline helpers ----
    const int xrow = tid >> 2;                 // 0..63
    const uint32_t xdst = sXraw + (uint32_t)xrow * 256u;

    auto cp_x = [&](int chunk) {
        const float* src = xb + (size_t)(chunk * KCHUNK + xrow) * HW_DIM;
#pragma unroll
        for (int i = 0; i < 4; i++) {
            int seg = (tid & 3) + i * 4;       // 0..15 (16B segments of 256B row)
            CP16(xdst + (uint32_t)seg * 16u, src + seg * 4);
        }
    };
    auto cp_w = [&](int chunk) {
        const char* wsrc = (const char*)&g_wt[chunk][0];
#pragma unroll
        for (int i = 0; i < 4; i++)
            CP16(sW + (uint32_t)(tid * 16 + i * 4096), wsrc + tid * 16 + i * 4096);
    };
    auto convert_x = [&]() {
        const int l16 = tid & 15;
#pragma unroll
        for (int kk = 0; kk < 4; kk++) {
            const int k = kk * 16 + (tid >> 4);
            float4 v;
            asm volatile("ld.shared.v4.f32 {%0,%1,%2,%3}, [%4];"
                         : "=f"(v.x), "=f"(v.y), "=f"(v.z), "=f"(v.w)
                         : "r"(sXraw + (uint32_t)k * 256u + (uint32_t)l16 * 16u));
            __half2 hi01 = __floats2half2_rn(v.x, v.y);
            __half2 hi23 = __floats2half2_rn(v.z, v.w);
            float2 f01 = __half22float2(hi01);
            float2 f23 = __half22float2(hi23);
            __half2 lo01 = __floats2half2_rn(v.x - f01.x, v.y - f01.y);
            __half2 lo23 = __floats2half2_rn(v.z - f23.x, v.w - f23.y);
            uint32_t h01, h23, l01, l23;
            memcpy(&h01, &hi01, 4); memcpy(&h23, &hi23, 4);
            memcpy(&l01, &lo01, 4); memcpy(&l23, &lo23, 4);
            uint32_t addr = (uint32_t)k * 128u
                          + (uint32_t)((((uint32_t)(l16 >> 1)) ^ (k & 7)) << 4)
                          + (uint32_t)((l16 & 1) << 3);
            asm volatile("st.shared.v2.b32 [%0], {%1,%2};" :: "r"(sXh + addr), "r"(h01), "r"(h23) : "memory");
            asm volatile("st.shared.v2.b32 [%0], {%1,%2};" :: "r"(sXl + addr), "r"(l01), "r"(l23) : "memory");
        }
    };

    // ---- prologue: stage chunk 0 ----
    cp_x(0);
    cp_w(0);
    CP_COMMIT();
    CP_WAIT0();
    __syncthreads();
    convert_x();
    __syncthreads();

    for (int chunk = 0; chunk < NCHUNK; chunk++) {
        if (chunk < NCHUNK - 1) {
            cp_x(chunk + 1);
            CP_COMMIT();
        }

        // ---- MMA: 4 k-steps of 16, 2 terms (Wh*Xh + Wh*Xl) ----
#pragma unroll
        for (int ks = 0; ks < 4; ks++) {
            uint32_t bh[2][2], bl[2][2];
            const uint32_t kRow = (uint32_t)(ks * 16 + (lane & 15));
#pragma unroll
            for (int nt = 0; nt < 2; nt++) {
                uint32_t addr = kRow * 128u
                              + (uint32_t)((((uint32_t)(wp * 2 + nt)) ^ (kRow & 7u)) << 4);
                ldsm_x2_t(bh[nt], sXh + addr);
                ldsm_x2_t(bl[nt], sXl + addr);
            }
            // A fragments 2 mt at a time to bound live registers (4 CTA/SM target)
#pragma unroll
            for (int mth = 0; mth < 2; mth++) {
                uint32_t ah[2][4];
#pragma unroll
                for (int m2 = 0; m2 < 2; m2++) {
                    uint32_t off = aBase[mth * 2 + m2] + (uint32_t)ks * 32u;
                    ldsm_x4(ah[m2], sW + (off ^ ((off >> 3) & 0x70u)));
                }
#pragma unroll
                for (int m2 = 0; m2 < 2; m2++)
#pragma unroll
                    for (int nt = 0; nt < 2; nt++) {
                        mma_f16(acc[mth * 2 + m2][nt], ah[m2], bh[nt]);
                        mma_f16(acc[mth * 2 + m2][nt], ah[m2], bl[nt]);
                    }
            }
        }

        __syncthreads();   // MMA done reading W, Xh, Xl

        if (chunk < NCHUNK - 1) {
            cp_w(chunk + 1);
            CP_COMMIT();
            CP_WAIT0();
            __syncthreads();
            convert_x();
            __syncthreads();
        }
    }

    // ---- epilogue: logits d = sum_o (w2[0][o]-w2[1][o]) * relu(h + b1[o]) ----
    float wdv[8], b1v[8];
#pragma unroll
    for (int mt = 0; mt < 4; mt++)
#pragma unroll
        for (int h = 0; h < 2; h++) {
            int o = o0 + mt * 16 + (lane >> 2) + h * 8;
            wdv[mt * 2 + h] = w2[o] - w2[CH_DIM + o];
            b1v[mt * 2 + h] = b1[o];
        }

    float part[2][2];
#pragma unroll
    for (int nt = 0; nt < 2; nt++)
#pragma unroll
        for (int c = 0; c < 2; c++) {
            float s = 0.0f;
#pragma unroll
            for (int mt = 0; mt < 4; mt++)
#pragma unroll
                for (int h = 0; h < 2; h++)
                    s += wdv[mt * 2 + h] * fmaxf(acc[mt][nt][h * 2 + c] + b1v[mt * 2 + h], 0.0f);
            part[nt][c] = s;
        }
#pragma unroll
    for (int off = 4; off < 32; off <<= 1)
#pragma unroll
        for (int nt = 0; nt < 2; nt++)
#pragma unroll
            for (int c = 0; c < 2; c++)
                part[nt][c] += __shfl_xor_sync(0xFFFFFFFFu, part[nt][c], off);

    if (lane < 4) {
#pragma unroll
        for (int nt = 0; nt < 2; nt++)
#pragma unroll
            for (int c = 0; c < 2; c++)
                atomicAdd(&logit_s[p0 + nt * 8 + lane * 2 + c], part[nt][c]);
    }
    __syncthreads();

    const float db2 = b2[0] - b2[1];
    const size_t OFFX = (size_t)B_DIM * C_DIM * HW_DIM;
    if (tid < TILE_PIX) {
        float d  = logit_s[tid] + db2;
        float m0 = 1.0f / (1.0f + expf(-d));
        m0_s[tid] = m0;
        m1_s[tid] = 1.0f - m0;
        float* mout = out + 2 * OFFX + (size_t)b * 2 * HW_DIM + pix0 + tid;
        mout[0]      = m0;
        mout[HW_DIM] = 1.0f - m0;
    }
    __syncthreads();

    // ---- multiply sweep: x0 = x*m0, x1 = x*m1 ----
    float* out0 = out + (size_t)b * C_DIM * HW_DIM + pix0;
    float* out1 = out0 + OFFX;
    const float4* m0v4 = (const float4*)m0_s;
    const float4* m1v4 = (const float4*)m1_s;

    for (int it = tid; it < C_DIM * (TILE_PIX / 4); it += 256) {
        int c    = it >> 4;
        int col4 = it & 15;
        size_t off = (size_t)c * HW_DIM + col4 * 4;
        float4 xv;
        asm volatile("ld.global.cs.v4.f32 {%0,%1,%2,%3}, [%4];"
                     : "=f"(xv.x), "=f"(xv.y), "=f"(xv.z), "=f"(xv.w)
                     : "l"(xb + off));
        float4 m0v = m0v4[col4];
        float4 m1v = m1v4[col4];
        float4 r0 = make_float4(xv.x * m0v.x, xv.y * m0v.y, xv.z * m0v.z, xv.w * m0v.w);
        float4 r1 = make_float4(xv.x * m1v.x, xv.y * m1v.y, xv.z * m1v.z, xv.w * m1v.w);
        asm volatile("st.global.cs.v4.f32 [%0], {%1,%2,%3,%4};"
                     :: "l"(out0 + off), "f"(r0.x), "f"(r0.y), "f"(r0.z), "f"(r0.w) : "memory");
        asm volatile("st.global.cs.v4.f32 [%0], {%1,%2,%3,%4};"
                     :: "l"(out1 + off), "f"(r1.x), "f"(r1.y), "f"(r1.z), "f"(r1.w) : "memory");
    }
}

extern "C" void kernel_launch(void* const* d_in, const int* in_sizes, int n_in,
                              void* d_out, int out_size) {
    const float* x  = (const float*)d_in[0];
    const float* w1 = (const float*)d_in[1];
    const float* b1 = (const float*)d_in[2];
    const float* w2 = (const float*)d_in[3];
    const float* b2 = (const float*)d_in[4];
    float* out = (float*)d_out;

    cudaFuncSetAttribute(lcs_main, cudaFuncAttributeMaxDynamicSharedMemorySize, 49152);

    lcs_prep_w<<<256, 256>>>(w1);

    int nblocks = B_DIM * NTILES;   // 16 * 144 = 2304
    lcs_main<<<nblocks, 256, 49152>>>(x, b1, w2, b2, out);
}